// round 14
// baseline (speedup 1.0000x reference)
#include <cuda_runtime.h>
#include <cuda_fp16.h>
#include <math.h>
#include <stdint.h>

// Problem constants
#define BB   32
#define SS   100
#define SH   50        // q rows per attention block (split 2)
#define DD   256
#define HH   4
#define DK_  64
#define LL   3
#define MM   (BB*SS)      // 3200
#define DFF_ 1024
#define NOUT 50001

// ---------------- scratch (no allocation allowed -> device globals) ----------------
__device__ float g_h[MM*DD];
__device__ float g_q[MM*DD];
__device__ float g_k1[MM*DD];
__device__ float g_k2[MM*DD];
__device__ float g_v[MM*DD];
// fp16 operand network
__device__ __align__(16) __half g_hn_h[MM*DD];
__device__ __align__(16) __half g_temb_h[MM*DD];
__device__ __align__(16) __half g_ctx_h[MM*DD];
__device__ __align__(16) __half g_ffn_h[MM*DFF_];
__device__ __align__(16) __half g_hh[MM*DD];
// fp16 weights
__device__ __align__(16) __half g_Wqh[LL*DD*DD];
__device__ __align__(16) __half g_Wkh[LL*DD*DD];
__device__ __align__(16) __half g_Wth[LL*DD*DD];
__device__ __align__(16) __half g_Wvh[LL*DD*DD];
__device__ __align__(16) __half g_Woh[LL*DD*DD];
__device__ __align__(16) __half g_w1h[LL*DFF_*DD];
__device__ __align__(16) __half g_w2h[LL*DD*DFF_];
__device__ __align__(16) __half g_outwh[(size_t)NOUT*DD];

// ---------------- fp32 -> fp16 convert ----------------
__global__ void f2h_kernel(const float* __restrict__ src, __half* __restrict__ dst, int n4) {
    int i = blockIdx.x*blockDim.x + threadIdx.x;
    if (i < n4) {
        float4 v = ((const float4*)src)[i];
        ((__half2*)dst)[i*2]   = __floats2half2_rn(v.x, v.y);
        ((__half2*)dst)[i*2+1] = __floats2half2_rn(v.z, v.w);
    }
}

// ---------------- embedding + time embedding ----------------
__global__ void embed_kernel(const int* __restrict__ x, const float* __restrict__ times,
                             const float* __restrict__ token_emb, const float* __restrict__ pos_emb,
                             const float* __restrict__ sel_w, const float* __restrict__ sel_b,
                             const float* __restrict__ time_w, const float* __restrict__ time_b,
                             const float* __restrict__ per_w, const float* __restrict__ per_b)
{
    int bs = blockIdx.x;
    int s  = bs % SS;
    int d  = threadIdx.x;
    __shared__ float g[64];
    float tval = times[bs];
    if (d < 64) {
        float t = tval * (1.0f/180.0f) * sel_w[d] + sel_b[d];
        g[d] = 1.0f - tanhf(t*t);
    }
    __syncthreads();
    float ang = 2.0f * 3.14159265358979323846f * tval / 24.0f;
    float sa = sinf(ang), ca = cosf(ang);
    float feat = time_b[d];
    const float* tw = time_w + d*64;
    #pragma unroll 16
    for (int j = 0; j < 64; j++) feat += g[j] * tw[j];
    float per = sa*per_w[d*2+0] + ca*per_w[d*2+1] + per_b[d];
    g_temb_h[bs*DD + d] = __float2half(feat + per);
    int tok = x[bs];
    g_h[bs*DD + d] = token_emb[(size_t)tok*DD + d] + pos_emb[s*DD + d];
}

// ---------------- LayerNorm (torch variant) -> half output ----------------
__global__ void ln_kernel(const float* __restrict__ x, const float* __restrict__ a,
                          const float* __restrict__ b, __half* __restrict__ y)
{
    int row = blockIdx.x;
    int d = threadIdx.x;
    int lane = d & 31, warp = d >> 5;
    __shared__ float ws1[8], ws2[8];
    float v = x[row*DD + d];
    float s = v;
    #pragma unroll
    for (int o = 16; o > 0; o >>= 1) s += __shfl_xor_sync(0xffffffff, s, o);
    if (lane == 0) ws1[warp] = s;
    __syncthreads();
    float tot = 0.f;
    #pragma unroll
    for (int i = 0; i < 8; i++) tot += ws1[i];
    float mean = tot * (1.0f/DD);
    float diff = v - mean;
    float s2 = diff*diff;
    #pragma unroll
    for (int o = 16; o > 0; o >>= 1) s2 += __shfl_xor_sync(0xffffffff, s2, o);
    if (lane == 0) ws2[warp] = s2;
    __syncthreads();
    float tot2 = 0.f;
    #pragma unroll
    for (int i = 0; i < 8; i++) tot2 += ws2[i];
    float stdv = sqrtf(tot2 * (1.0f/(DD-1)));
    y[row*DD + d] = __float2half(a[d]*diff/(stdv + 1e-6f) + b[d]);
}

// ---------------- GELU ----------------
__device__ __forceinline__ float gelu_f(float x) {
    const float c = 0.7978845608028654f;   // sqrt(2/pi)
    float x3 = x*x*x;
    return 0.5f*x*(1.0f + tanhf(c*(x + 0.044715f*x3)));
}

// ---------------- raw mma.m16n8k16 fp16 (fp32 accum) ----------------
__device__ __forceinline__ void mma16(float* c, const uint32_t* a, const uint32_t* b) {
    asm volatile("mma.sync.aligned.m16n8k16.row.col.f32.f16.f16.f32 "
        "{%0,%1,%2,%3}, {%4,%5,%6,%7}, {%8,%9}, {%0,%1,%2,%3};"
        : "+f"(c[0]), "+f"(c[1]), "+f"(c[2]), "+f"(c[3])
        : "r"(a[0]), "r"(a[1]), "r"(a[2]), "r"(a[3]), "r"(b[0]), "r"(b[1]));
}

// ---------------- GEMM v1: 128x128 tile, 8 warps (2Mx4N), warp 64x32, BK=32, double buffered ----
// epi: 0 = C fp32; 1 = Ch = half(gelu); 2 = C fp32 += res; 3 = C += res AND Ch = half(C)
__device__ __forceinline__ void gemm_mma_body(const __half* __restrict__ A,
                                              const __half* __restrict__ W,
                                              const float* __restrict__ bias,
                                              const float* __restrict__ res,
                                              float* __restrict__ C,
                                              __half* __restrict__ Ch,
                                              int N, int K, int row0, int col0, int epi)
{
    __shared__ uint32_t As[2][2048];
    __shared__ uint32_t Bs[2][2048];
    int tid = threadIdx.x;
    int warp = tid >> 5, lane = tid & 31;
    int wm = warp & 1, wn = warp >> 1;

    float acc[4][4][4];
    #pragma unroll
    for (int i = 0; i < 4; i++)
        #pragma unroll
        for (int j = 0; j < 4; j++)
            #pragma unroll
            for (int q = 0; q < 4; q++) acc[i][j][q] = 0.f;

    int lrow = tid >> 1;
    int sK   = tid & 1;          // which k16 chunk of the BK=32 tile
    const __half* Ag = A + (size_t)(row0 + lrow)*K + sK*16;
    int wrow = col0 + lrow;
    const __half* Wg = W + (size_t)wrow*K + sK*16;
    bool wv = wrow < N;

    int t = lrow >> 4, rp = lrow & 15;
    int aoff = sK*1024 + t*128 + (rp & 7)*16 + (rp >> 3);
    int u = lrow >> 3, np = lrow & 7;
    int boff = sK*1024 + u*64 + np*8;
    const uint4 z4 = make_uint4(0u,0u,0u,0u);

    {
        uint4 a0 = *(const uint4*)(Ag);
        uint4 a1 = *(const uint4*)(Ag + 8);
        uint4 w0 = wv ? *(const uint4*)(Wg)     : z4;
        uint4 w1 = wv ? *(const uint4*)(Wg + 8) : z4;
        uint32_t* ab = &As[0][aoff];
        ab[0]=a0.x; ab[4]=a0.y; ab[8]=a0.z;  ab[12]=a0.w;
        ab[2]=a1.x; ab[6]=a1.y; ab[10]=a1.z; ab[14]=a1.w;
        uint32_t* bb = &Bs[0][boff];
        bb[0]=w0.x; bb[2]=w0.y; bb[4]=w0.z; bb[6]=w0.w;
        bb[1]=w1.x; bb[3]=w1.y; bb[5]=w1.z; bb[7]=w1.w;
    }
    __syncthreads();

    int buf = 0;
    for (int kk = 32; kk <= K; kk += 32) {
        uint4 na0, na1, nw0, nw1;
        bool more = (kk < K);
        if (more) {
            na0 = *(const uint4*)(Ag + kk);
            na1 = *(const uint4*)(Ag + kk + 8);
            nw0 = wv ? *(const uint4*)(Wg + kk)     : z4;
            nw1 = wv ? *(const uint4*)(Wg + kk + 8) : z4;
        }
        const uint32_t* Ab = As[buf];
        const uint32_t* Bb = Bs[buf];
        #pragma unroll
        for (int s = 0; s < 2; s++) {
            uint32_t af[4][4], bf[4][2];
            #pragma unroll
            for (int i = 0; i < 4; i++) {
                uint4 v = *(const uint4*)(Ab + s*1024 + (wm*4 + i)*128 + lane*4);
                af[i][0] = v.x; af[i][1] = v.y; af[i][2] = v.z; af[i][3] = v.w;
            }
            #pragma unroll
            for (int j = 0; j < 4; j++) {
                uint2 v = *(const uint2*)(Bb + s*1024 + (wn*4 + j)*64 + lane*2);
                bf[j][0] = v.x; bf[j][1] = v.y;
            }
            #pragma unroll
            for (int i = 0; i < 4; i++)
                #pragma unroll
                for (int j = 0; j < 4; j++)
                    mma16(acc[i][j], af[i], bf[j]);
        }
        if (more) {
            uint32_t* ab = &As[buf^1][aoff];
            ab[0]=na0.x; ab[4]=na0.y; ab[8]=na0.z;  ab[12]=na0.w;
            ab[2]=na1.x; ab[6]=na1.y; ab[10]=na1.z; ab[14]=na1.w;
            uint32_t* bb = &Bs[buf^1][boff];
            bb[0]=nw0.x; bb[2]=nw0.y; bb[4]=nw0.z; bb[6]=nw0.w;
            bb[1]=nw1.x; bb[3]=nw1.y; bb[5]=nw1.z; bb[7]=nw1.w;
            __syncthreads();
            buf ^= 1;
        }
    }

    int r = lane >> 2, c2 = (lane & 3) * 2;
    #pragma unroll
    for (int i = 0; i < 4; i++) {
        int gr = row0 + wm*64 + i*16 + r;
        size_t rb0 = (size_t)gr * N;
        size_t rb1 = (size_t)(gr + 8) * N;
        #pragma unroll
        for (int j = 0; j < 4; j++) {
            int gc = col0 + wn*32 + j*8 + c2;
            const float* cp = acc[i][j];
            if (gc + 1 < N) {
                float b0 = bias[gc], b1 = bias[gc+1];
                float v0 = cp[0] + b0, v1 = cp[1] + b1;
                float v2 = cp[2] + b0, v3 = cp[3] + b1;
                if (epi == 0) {
                    C[rb0 + gc] = v0; C[rb0 + gc + 1] = v1;
                    C[rb1 + gc] = v2; C[rb1 + gc + 1] = v3;
                } else if (epi == 1) {
                    *(__half2*)(Ch + rb0 + gc) = __floats2half2_rn(gelu_f(v0), gelu_f(v1));
                    *(__half2*)(Ch + rb1 + gc) = __floats2half2_rn(gelu_f(v2), gelu_f(v3));
                } else {
                    v0 += res[rb0 + gc]; v1 += res[rb0 + gc + 1];
                    v2 += res[rb1 + gc]; v3 += res[rb1 + gc + 1];
                    C[rb0 + gc] = v0; C[rb0 + gc + 1] = v1;
                    C[rb1 + gc] = v2; C[rb1 + gc + 1] = v3;
                    if (epi == 3) {
                        *(__half2*)(Ch + rb0 + gc) = __floats2half2_rn(v0, v1);
                        *(__half2*)(Ch + rb1 + gc) = __floats2half2_rn(v2, v3);
                    }
                }
            } else if (gc < N) {
                float b0 = bias[gc];
                float v0 = cp[0] + b0, v2 = cp[2] + b0;
                if (epi == 0) {
                    C[rb0 + gc] = v0; C[rb1 + gc] = v2;
                } else if (epi == 1) {
                    Ch[rb0 + gc] = __float2half(gelu_f(v0));
                    Ch[rb1 + gc] = __float2half(gelu_f(v2));
                } else {
                    v0 += res[rb0 + gc]; v2 += res[rb1 + gc];
                    C[rb0 + gc] = v0; C[rb1 + gc] = v2;
                    if (epi == 3) {
                        Ch[rb0 + gc] = __float2half(v0);
                        Ch[rb1 + gc] = __float2half(v2);
                    }
                }
            }
        }
    }
}

__global__ void __launch_bounds__(256, 2) gemm_mma(const __half* __restrict__ A,
                                                   const __half* __restrict__ W,
                                                   const float* __restrict__ bias,
                                                   const float* __restrict__ res,
                                                   float* __restrict__ C,
                                                   __half* __restrict__ Ch,
                                                   int N, int K, int epi)
{
    gemm_mma_body(A, W, bias, res, C, Ch, N, K, blockIdx.y*128, blockIdx.x*128, epi);
}

__global__ void __launch_bounds__(256, 2) qktv_gemm(const __half* __restrict__ hn,
                                                    const __half* __restrict__ temb,
                                                    const __half* __restrict__ Wq, const __half* __restrict__ Wk,
                                                    const __half* __restrict__ Wt, const __half* __restrict__ Wv,
                                                    const float* __restrict__ bq, const float* __restrict__ bk,
                                                    const float* __restrict__ bt, const float* __restrict__ bv,
                                                    float* __restrict__ q, float* __restrict__ k1,
                                                    float* __restrict__ k2, float* __restrict__ v)
{
    int z = blockIdx.z;
    const __half* A = (z == 2) ? temb : hn;
    const __half* W = (z == 0) ? Wq : (z == 1) ? Wk : (z == 2) ? Wt : Wv;
    const float* b = (z == 0) ? bq : (z == 1) ? bk : (z == 2) ? bt : bv;
    float*       C = (z == 0) ? q  : (z == 1) ? k1 : (z == 2) ? k2 : v;
    gemm_mma_body(A, W, b, nullptr, C, nullptr, DD, DD, blockIdx.y*128, blockIdx.x*128, 0);
}

// ---------------- GEMM small: 64x64 tile, 4 warps (2Mx2N), warp 32x32, BK=16, double buffered ----
__global__ void __launch_bounds__(128) gemm_s(const __half* __restrict__ A,
                                              const __half* __restrict__ W,
                                              const float* __restrict__ bias,
                                              const float* __restrict__ res,
                                              float* __restrict__ C,
                                              __half* __restrict__ Ch,
                                              int N, int K, int epi)
{
    __shared__ uint32_t As[2][512];
    __shared__ uint32_t Bs[2][512];
    int tid = threadIdx.x;
    int warp = tid >> 5, lane = tid & 31;
    int wm = warp & 1, wn = warp >> 1;
    int row0 = blockIdx.y*64, col0 = blockIdx.x*64;

    float acc[2][4][4];
    #pragma unroll
    for (int i = 0; i < 2; i++)
        #pragma unroll
        for (int j = 0; j < 4; j++)
            #pragma unroll
            for (int q = 0; q < 4; q++) acc[i][j][q] = 0.f;

    int lrow = tid >> 1;          // 0..63
    int sK   = tid & 1;
    const __half* Ag = A + (size_t)(row0 + lrow)*K + sK*8;
    int wrow = col0 + lrow;
    const __half* Wg = W + (size_t)wrow*K + sK*8;
    bool wv = wrow < N;

    int t = lrow >> 4, rp = lrow & 15;        // t: 0..3
    int aoff = t*128 + (rp & 7)*16 + (rp >> 3) + sK*2;
    int u = lrow >> 3, np = lrow & 7;         // u: 0..7
    int boff = u*64 + np*8 + sK;
    const uint4 z4 = make_uint4(0u,0u,0u,0u);

    {
        uint4 a = *(const uint4*)(Ag);
        uint4 w = wv ? *(const uint4*)(Wg) : z4;
        uint32_t* ab = &As[0][aoff];
        ab[0]=a.x; ab[4]=a.y; ab[8]=a.z; ab[12]=a.w;
        uint32_t* bb = &Bs[0][boff];
        bb[0]=w.x; bb[2]=w.y; bb[4]=w.z; bb[6]=w.w;
    }
    __syncthreads();

    int buf = 0;
    for (int kk = 16; kk <= K; kk += 16) {
        uint4 na, nw;
        bool more = (kk < K);
        if (more) {
            na = *(const uint4*)(Ag + kk);
            nw = wv ? *(const uint4*)(Wg + kk) : z4;
        }
        const uint32_t* Ab = As[buf];
        const uint32_t* Bb = Bs[buf];
        uint32_t af[2][4], bf[4][2];
        #pragma unroll
        for (int i = 0; i < 2; i++) {
            uint4 v = *(const uint4*)(Ab + (wm*2 + i)*128 + lane*4);
            af[i][0] = v.x; af[i][1] = v.y; af[i][2] = v.z; af[i][3] = v.w;
        }
        #pragma unroll
        for (int j = 0; j < 4; j++) {
            uint2 v = *(const uint2*)(Bb + (wn*4 + j)*64 + lane*2);
            bf[j][0] = v.x; bf[j][1] = v.y;
        }
        #pragma unroll
        for (int i = 0; i < 2; i++)
            #pragma unroll
            for (int j = 0; j < 4; j++)
                mma16(acc[i][j], af[i], bf[j]);
        if (more) {
            uint32_t* ab = &As[buf^1][aoff];
            ab[0]=na.x; ab[4]=na.y; ab[8]=na.z; ab[12]=na.w;
            uint32_t* bb = &Bs[buf^1][boff];
            bb[0]=nw.x; bb[2]=nw.y; bb[4]=nw.z; bb[6]=nw.w;
            __syncthreads();
            buf ^= 1;
        }
    }

    int r = lane >> 2, c2 = (lane & 3) * 2;
    #pragma unroll
    for (int i = 0; i < 2; i++) {
        int gr = row0 + wm*32 + i*16 + r;
        size_t rb0 = (size_t)gr * N;
        size_t rb1 = (size_t)(gr + 8) * N;
        #pragma unroll
        for (int j = 0; j < 4; j++) {
            int gc = col0 + wn*32 + j*8 + c2;
            const float* cp = acc[i][j];
            if (gc + 1 < N) {
                float b0 = bias[gc], b1 = bias[gc+1];
                float v0 = cp[0] + b0, v1 = cp[1] + b1;
                float v2 = cp[2] + b0, v3 = cp[3] + b1;
                if (epi == 0) {
                    C[rb0 + gc] = v0; C[rb0 + gc + 1] = v1;
                    C[rb1 + gc] = v2; C[rb1 + gc + 1] = v3;
                } else if (epi == 1) {
                    *(__half2*)(Ch + rb0 + gc) = __floats2half2_rn(gelu_f(v0), gelu_f(v1));
                    *(__half2*)(Ch + rb1 + gc) = __floats2half2_rn(gelu_f(v2), gelu_f(v3));
                } else {
                    v0 += res[rb0 + gc]; v1 += res[rb0 + gc + 1];
                    v2 += res[rb1 + gc]; v3 += res[rb1 + gc + 1];
                    C[rb0 + gc] = v0; C[rb0 + gc + 1] = v1;
                    C[rb1 + gc] = v2; C[rb1 + gc + 1] = v3;
                    if (epi == 3) {
                        *(__half2*)(Ch + rb0 + gc) = __floats2half2_rn(v0, v1);
                        *(__half2*)(Ch + rb1 + gc) = __floats2half2_rn(v2, v3);
                    }
                }
            } else if (gc < N) {
                float b0 = bias[gc];
                float v0 = cp[0] + b0, v2 = cp[2] + b0;
                if (epi == 0) {
                    C[rb0 + gc] = v0; C[rb1 + gc] = v2;
                } else if (epi == 1) {
                    Ch[rb0 + gc] = __float2half(gelu_f(v0));
                    Ch[rb1 + gc] = __float2half(gelu_f(v2));
                } else {
                    v0 += res[rb0 + gc]; v2 += res[rb1 + gc];
                    C[rb0 + gc] = v0; C[rb1 + gc] = v2;
                    if (epi == 3) {
                        Ch[rb0 + gc] = __float2half(v0);
                        Ch[rb1 + gc] = __float2half(v2);
                    }
                }
            }
        }
    }
}

// ---------------- attention: grid (H, B, 2) -- fp32 K/V (R12 version), ctx written as half ----
#define KTP 104

__global__ void __launch_bounds__(512) attn_kernel(
        const float* __restrict__ q, const float* __restrict__ k1,
        const float* __restrict__ k2, const float* __restrict__ v,
        const int* __restrict__ x, const float* __restrict__ ml,
        __half* __restrict__ ctx)
{
    extern __shared__ float sm[];
    float* qs  = sm;                    // SH*64
    float* vs  = qs  + SH*DK_;          // SS*64
    float* kct = vs  + SS*DK_;          // 64*KTP
    float* sc  = kct + DK_*KTP;         // SH*SS
    float* offs= sc + SH*SS;            // SS
    int h = blockIdx.x, b = blockIdx.y, z = blockIdx.z;
    int tid = threadIdx.x;
    int lane = tid & 31, warp = tid >> 5;
    int base = b*SS*DD + h*DK_;
    int q0 = z*SH;

    for (int idx = tid; idx < SS*DK_; idx += 512) {
        int s = idx >> 6, d = idx & 63;
        int gi = base + s*DD + d;
        vs[idx] = v[gi];
        bool kp = x[b*SS + s] > 0;
        float k2v = k2[gi];
        kct[d*KTP + s] = kp ? (k1[gi] + k2v) : k2v;
    }
    for (int idx = tid; idx < SH*DK_; idx += 512) {
        int s = idx >> 6, d = idx & 63;
        qs[idx] = q[base + (q0 + s)*DD + d];
    }
    if (tid < SS) offs[tid] = (x[b*SS + tid] > 0) ? 0.0f : -1e9f;
    __syncthreads();

    const float scale = 0.125f;
    for (int g = tid; g < SH*25; g += 512) {
        int qi = g / 25;
        int kg = (g - qi*25) * 4;
        const float* qp = qs + qi*DK_;
        float4 s1 = make_float4(0.f,0.f,0.f,0.f);
        #pragma unroll 8
        for (int d = 0; d < DK_; d++) {
            float qv = qp[d];
            float4 b1 = *(const float4*)(kct + d*KTP + kg);
            s1.x += qv*b1.x; s1.y += qv*b1.y; s1.z += qv*b1.z; s1.w += qv*b1.w;
        }
        float* sr = sc + qi*SS + kg;
        const float* op = offs + kg;
        sr[0] = s1.x*scale + op[0];
        sr[1] = s1.y*scale + op[1];
        sr[2] = s1.z*scale + op[2];
        sr[3] = s1.w*scale + op[3];
    }
    __syncthreads();

    for (int r = warp; r < SH; r += 16) {
        float* row = sc + r*SS;
        float mx = -1e30f;
        for (int c = lane; c < SS; c += 32) mx = fmaxf(mx, row[c]);
        #pragma unroll
        for (int o = 16; o > 0; o >>= 1) mx = fmaxf(mx, __shfl_xor_sync(0xffffffff, mx, o));
        float sum = 0.f;
        for (int c = lane; c < SS; c += 32) {
            float e = __expf(row[c] - mx);
            row[c] = e; sum += e;
        }
        #pragma unroll
        for (int o = 16; o > 0; o >>= 1) sum += __shfl_xor_sync(0xffffffff, sum, o);
        float inv = 1.0f / sum;
        const float* mlr = ml + (q0 + r)*SS;
        for (int c = lane; c < SS; c += 32) {
            float zz = mlr[c];
            float sg = 1.0f / (1.0f + __expf(-zz));
            row[c] *= inv * sg;
        }
    }
    __syncthreads();

    for (int o = tid; o < SH*16; o += 512) {
        int qi = o >> 4;
        int dg = (o & 15) * 4;
        const float* sr = sc + qi*SS;
        const float* vp = vs + dg;
        float4 a = make_float4(0.f,0.f,0.f,0.f);
        #pragma unroll 4
        for (int k = 0; k < SS; k++) {
            float p = sr[k];
            float4 vv = *(const float4*)(vp + k*DK_);
            a.x += p*vv.x; a.y += p*vv.y; a.z += p*vv.z; a.w += p*vv.w;
        }
        __half2* dst = (__half2*)(ctx + base + (q0 + qi)*DD + dg);
        dst[0] = __floats2half2_rn(a.x, a.y);
        dst[1] = __floats2half2_rn(a.z, a.w);
    }
}

// ---------------- host launcher ----------------
extern "C" void kernel_launch(void* const* d_in, const int* in_sizes, int n_in,
                              void* d_out, int out_size)
{
    (void)in_sizes; (void)n_in; (void)out_size;
    const int*   x         = (const int*)  d_in[0];
    const float* times     = (const float*)d_in[1];
    const float* token_emb = (const float*)d_in[2];
    const float* pos_emb   = (const float*)d_in[3];
    const float* sel_w     = (const float*)d_in[4];
    const float* sel_b     = (const float*)d_in[5];
    const float* time_w    = (const float*)d_in[6];
    const float* time_b    = (const float*)d_in[7];
    const float* per_w     = (const float*)d_in[8];
    const float* per_b     = (const float*)d_in[9];
    const float* Wq        = (const float*)d_in[10];
    const float* Wk        = (const float*)d_in[11];
    const float* Wt        = (const float*)d_in[12];
    const float* Wv        = (const float*)d_in[13];
    const float* Wo        = (const float*)d_in[14];
    const float* bq        = (const float*)d_in[15];
    const float* bk        = (const float*)d_in[16];
    const float* bt        = (const float*)d_in[17];
    const float* bv        = (const float*)d_in[18];
    const float* bo        = (const float*)d_in[19];
    const float* mask_log  = (const float*)d_in[20];
    const float* ln1_a     = (const float*)d_in[21];
    const float* ln1_b     = (const float*)d_in[22];
    const float* ln2_a     = (const float*)d_in[23];
    const float* ln2_b     = (const float*)d_in[24];
    const float* ffn_w1    = (const float*)d_in[25];
    const float* ffn_b1    = (const float*)d_in[26];
    const float* ffn_w2    = (const float*)d_in[27];
    const float* ffn_b2    = (const float*)d_in[28];
    const float* out_w     = (const float*)d_in[29];
    const float* out_b     = (const float*)d_in[30];
    float* out = (float*)d_out;

    float *ph,*pq,*pk1,*pk2,*pv;
    __half *phn,*ptemb,*pctx,*pffn,*phh;
    __half *wq,*wk,*wt,*wv_,*wo,*w1,*w2,*wout;
    cudaGetSymbolAddress((void**)&ph,    g_h);
    cudaGetSymbolAddress((void**)&pq,    g_q);
    cudaGetSymbolAddress((void**)&pk1,   g_k1);
    cudaGetSymbolAddress((void**)&pk2,   g_k2);
    cudaGetSymbolAddress((void**)&pv,    g_v);
    cudaGetSymbolAddress((void**)&phn,   g_hn_h);
    cudaGetSymbolAddress((void**)&ptemb, g_temb_h);
    cudaGetSymbolAddress((void**)&pctx,  g_ctx_h);
    cudaGetSymbolAddress((void**)&pffn,  g_ffn_h);
    cudaGetSymbolAddress((void**)&phh,   g_hh);
    cudaGetSymbolAddress((void**)&wq,    g_Wqh);
    cudaGetSymbolAddress((void**)&wk,    g_Wkh);
    cudaGetSymbolAddress((void**)&wt,    g_Wth);
    cudaGetSymbolAddress((void**)&wv_,   g_Wvh);
    cudaGetSymbolAddress((void**)&wo,    g_Woh);
    cudaGetSymbolAddress((void**)&w1,    g_w1h);
    cudaGetSymbolAddress((void**)&w2,    g_w2h);
    cudaGetSymbolAddress((void**)&wout,  g_outwh);

    const int attn_smem = (SH*DK_ + SS*DK_ + DK_*KTP + SH*SS + SS)*(int)sizeof(float); // ~85.4 KB
    cudaFuncSetAttribute(attn_kernel, cudaFuncAttributeMaxDynamicSharedMemorySize, attn_smem);

    // weight conversion (kernels only -> graph-capturable)
    const int nDD = LL*DD*DD/4, nF = LL*DFF_*DD/4, nOut = NOUT*DD/4;
    f2h_kernel<<<(nDD+255)/256, 256>>>(Wq, wq, nDD);
    f2h_kernel<<<(nDD+255)/256, 256>>>(Wk, wk, nDD);
    f2h_kernel<<<(nDD+255)/256, 256>>>(Wt, wt, nDD);
    f2h_kernel<<<(nDD+255)/256, 256>>>(Wv, wv_, nDD);
    f2h_kernel<<<(nDD+255)/256, 256>>>(Wo, wo, nDD);
    f2h_kernel<<<(nF+255)/256, 256>>>(ffn_w1, w1, nF);
    f2h_kernel<<<(nF+255)/256, 256>>>(ffn_w2, w2, nF);
    f2h_kernel<<<(nOut+255)/256, 256>>>(out_w, wout, nOut);

    embed_kernel<<<MM, 256>>>(x, times, token_emb, pos_emb, sel_w, sel_b,
                              time_w, time_b, per_w, per_b);

    dim3 gF(8, 25);            // 128x128 tiles, N=1024
    dim3 gS(4, 50);            // 64x64 tiles, N=256
    dim3 gQKTV(2, 25, 4);
    for (int l = 0; l < LL; l++) {
        ln_kernel<<<MM, 256>>>(ph, ln1_a + l*DD, ln1_b + l*DD, phn);
        qktv_gemm<<<gQKTV, 256>>>(phn, ptemb,
                                  wq + (size_t)l*DD*DD, wk + (size_t)l*DD*DD,
                                  wt + (size_t)l*DD*DD, wv_ + (size_t)l*DD*DD,
                                  bq + l*DD, bk + l*DD, bt + l*DD, bv + l*DD,
                                  pq, pk1, pk2, pv);
        attn_kernel<<<dim3(HH, BB, 2), 512, attn_smem>>>(pq, pk1, pk2, pv, x,
                                                         mask_log + l*SS*SS, pctx);
        gemm_s<<<gS, 128>>>(pctx, wo + (size_t)l*DD*DD, bo + l*DD, ph, ph, nullptr, DD, DD, 2);
        ln_kernel<<<MM, 256>>>(ph, ln2_a + l*DD, ln2_b + l*DD, phn);
        gemm_mma<<<gF, 256>>>(phn, w1 + (size_t)l*DFF_*DD, ffn_b1 + l*DFF_,
                              nullptr, nullptr, pffn, DFF_, DD, 1);
        gemm_s<<<gS, 128>>>(pffn, w2 + (size_t)l*DD*DFF_, ffn_b2 + l*DD, ph, ph, phh, DD, DFF_, 3);
    }
    gemm_mma<<<dim3(391, 25), 256>>>(phh, wout, out_b, nullptr, out, nullptr, NOUT, DD, 0);
}

// round 15
// speedup vs baseline: 1.0724x; 1.0724x over previous
#include <cuda_runtime.h>
#include <cuda_fp16.h>
#include <math.h>
#include <stdint.h>

// Problem constants
#define BB   32
#define SS   100
#define SH   50        // q rows per attention block (split 2)
#define DD   256
#define HH   4
#define DK_  64
#define LL   3
#define MM   (BB*SS)      // 3200
#define DFF_ 1024
#define NOUT 50001

// ---------------- scratch (no allocation allowed -> device globals) ----------------
__device__ float g_h[MM*DD];
__device__ float g_q[MM*DD];
__device__ float g_k1[MM*DD];
__device__ float g_k2[MM*DD];
__device__ float g_v[MM*DD];
// fp16 operand network
__device__ __align__(16) __half g_hn_h[MM*DD];
__device__ __align__(16) __half g_temb_h[MM*DD];
__device__ __align__(16) __half g_ctx_h[MM*DD];
__device__ __align__(16) __half g_ffn_h[MM*DFF_];
__device__ __align__(16) __half g_hh[MM*DD];
// fp16 weights
__device__ __align__(16) __half g_Wqh[LL*DD*DD];
__device__ __align__(16) __half g_Wkh[LL*DD*DD];
__device__ __align__(16) __half g_Wth[LL*DD*DD];
__device__ __align__(16) __half g_Wvh[LL*DD*DD];
__device__ __align__(16) __half g_Woh[LL*DD*DD];
__device__ __align__(16) __half g_w1h[LL*DFF_*DD];
__device__ __align__(16) __half g_w2h[LL*DD*DFF_];
__device__ __align__(16) __half g_outwh[(size_t)NOUT*DD];

// ---------------- fp32 -> fp16 convert ----------------
__global__ void f2h_kernel(const float* __restrict__ src, __half* __restrict__ dst, int n4) {
    int i = blockIdx.x*blockDim.x + threadIdx.x;
    if (i < n4) {
        float4 v = ((const float4*)src)[i];
        ((__half2*)dst)[i*2]   = __floats2half2_rn(v.x, v.y);
        ((__half2*)dst)[i*2+1] = __floats2half2_rn(v.z, v.w);
    }
}

// one launch converts the 7 layer-weight tensors (segment offsets are compile-time)
__global__ void f2h7_kernel(const float* __restrict__ Wq, const float* __restrict__ Wk,
                            const float* __restrict__ Wt, const float* __restrict__ Wv,
                            const float* __restrict__ Wo, const float* __restrict__ w1f,
                            const float* __restrict__ w2f,
                            __half* __restrict__ wq, __half* __restrict__ wk,
                            __half* __restrict__ wt, __half* __restrict__ wv,
                            __half* __restrict__ wo, __half* __restrict__ w1,
                            __half* __restrict__ w2)
{
    const int nD  = LL*DD*DD/4;      // 49152
    const int nFF = LL*DFF_*DD/4;    // 196608
    int i = blockIdx.x*blockDim.x + threadIdx.x;
    const float* s; __half* d; int off;
    if (i < 5*nD) {
        int seg = i / nD; off = i - seg*nD;
        s = (seg==0)?Wq:(seg==1)?Wk:(seg==2)?Wt:(seg==3)?Wv:Wo;
        d = (seg==0)?wq:(seg==1)?wk:(seg==2)?wt:(seg==3)?wv:wo;
    } else {
        int j = i - 5*nD;
        if (j >= 2*nFF) return;
        int seg = j / nFF; off = j - seg*nFF;
        s = seg ? w2f : w1f;
        d = seg ? w2  : w1;
    }
    float4 v = ((const float4*)s)[off];
    ((__half2*)d)[off*2]   = __floats2half2_rn(v.x, v.y);
    ((__half2*)d)[off*2+1] = __floats2half2_rn(v.z, v.w);
}

// ---------------- embedding + time embedding ----------------
__global__ void embed_kernel(const int* __restrict__ x, const float* __restrict__ times,
                             const float* __restrict__ token_emb, const float* __restrict__ pos_emb,
                             const float* __restrict__ sel_w, const float* __restrict__ sel_b,
                             const float* __restrict__ time_w, const float* __restrict__ time_b,
                             const float* __restrict__ per_w, const float* __restrict__ per_b)
{
    int bs = blockIdx.x;
    int s  = bs % SS;
    int d  = threadIdx.x;
    __shared__ float g[64];
    float tval = times[bs];
    if (d < 64) {
        float t = tval * (1.0f/180.0f) * sel_w[d] + sel_b[d];
        g[d] = 1.0f - tanhf(t*t);
    }
    __syncthreads();
    float ang = 2.0f * 3.14159265358979323846f * tval / 24.0f;
    float sa = sinf(ang), ca = cosf(ang);
    float feat = time_b[d];
    const float* tw = time_w + d*64;
    #pragma unroll 16
    for (int j = 0; j < 64; j++) feat += g[j] * tw[j];
    float per = sa*per_w[d*2+0] + ca*per_w[d*2+1] + per_b[d];
    g_temb_h[bs*DD + d] = __float2half(feat + per);
    int tok = x[bs];
    g_h[bs*DD + d] = token_emb[(size_t)tok*DD + d] + pos_emb[s*DD + d];
}

// ---------------- LayerNorm (torch variant) -> half output ----------------
__global__ void ln_kernel(const float* __restrict__ x, const float* __restrict__ a,
                          const float* __restrict__ b, __half* __restrict__ y)
{
    int row = blockIdx.x;
    int d = threadIdx.x;
    int lane = d & 31, warp = d >> 5;
    __shared__ float ws1[8], ws2[8];
    float v = x[row*DD + d];
    float s = v;
    #pragma unroll
    for (int o = 16; o > 0; o >>= 1) s += __shfl_xor_sync(0xffffffff, s, o);
    if (lane == 0) ws1[warp] = s;
    __syncthreads();
    float tot = 0.f;
    #pragma unroll
    for (int i = 0; i < 8; i++) tot += ws1[i];
    float mean = tot * (1.0f/DD);
    float diff = v - mean;
    float s2 = diff*diff;
    #pragma unroll
    for (int o = 16; o > 0; o >>= 1) s2 += __shfl_xor_sync(0xffffffff, s2, o);
    if (lane == 0) ws2[warp] = s2;
    __syncthreads();
    float tot2 = 0.f;
    #pragma unroll
    for (int i = 0; i < 8; i++) tot2 += ws2[i];
    float stdv = sqrtf(tot2 * (1.0f/(DD-1)));
    y[row*DD + d] = __float2half(a[d]*diff/(stdv + 1e-6f) + b[d]);
}

// ---------------- GELU ----------------
__device__ __forceinline__ float gelu_f(float x) {
    const float c = 0.7978845608028654f;   // sqrt(2/pi)
    float x3 = x*x*x;
    return 0.5f*x*(1.0f + tanhf(c*(x + 0.044715f*x3)));
}

// ---------------- raw mma.m16n8k16 fp16 (fp32 accum) ----------------
__device__ __forceinline__ void mma16(float* c, const uint32_t* a, const uint32_t* b) {
    asm volatile("mma.sync.aligned.m16n8k16.row.col.f32.f16.f16.f32 "
        "{%0,%1,%2,%3}, {%4,%5,%6,%7}, {%8,%9}, {%0,%1,%2,%3};"
        : "+f"(c[0]), "+f"(c[1]), "+f"(c[2]), "+f"(c[3])
        : "r"(a[0]), "r"(a[1]), "r"(a[2]), "r"(a[3]), "r"(b[0]), "r"(b[1]));
}

// ---------------- GEMM v1: 128x128 tile, 8 warps (2Mx4N), warp 64x32, BK=16, double buffered ----
// epi: 0 = C fp32; 1 = Ch = half(gelu); 2 = C fp32 += res; 3 = C += res AND Ch = half(C)
__device__ __forceinline__ void gemm_mma_body(const __half* __restrict__ A,
                                              const __half* __restrict__ W,
                                              const float* __restrict__ bias,
                                              const float* __restrict__ res,
                                              float* __restrict__ C,
                                              __half* __restrict__ Ch,
                                              int N, int K, int row0, int col0, int epi)
{
    __shared__ uint32_t As[2][1024];
    __shared__ uint32_t Bs[2][1024];
    int tid = threadIdx.x;
    int warp = tid >> 5, lane = tid & 31;
    int wm = warp & 1, wn = warp >> 1;

    float acc[4][4][4];
    #pragma unroll
    for (int i = 0; i < 4; i++)
        #pragma unroll
        for (int j = 0; j < 4; j++)
            #pragma unroll
            for (int q = 0; q < 4; q++) acc[i][j][q] = 0.f;

    int lrow = tid >> 1;
    int sK   = tid & 1;
    const __half* Ag = A + (size_t)(row0 + lrow)*K + sK*8;
    int wrow = col0 + lrow;
    const __half* Wg = W + (size_t)wrow*K + sK*8;
    bool wv = wrow < N;

    int t = lrow >> 4, rp = lrow & 15;
    int aoff = t*128 + (rp & 7)*16 + (rp >> 3) + sK*2;
    int u = lrow >> 3, np = lrow & 7;
    int boff = u*64 + np*8 + sK;
    const uint4 z4 = make_uint4(0u,0u,0u,0u);

    {
        uint4 a = *(const uint4*)(Ag);
        uint4 w = wv ? *(const uint4*)(Wg) : z4;
        uint32_t* ab = &As[0][aoff];
        ab[0]=a.x; ab[4]=a.y; ab[8]=a.z; ab[12]=a.w;
        uint32_t* bb = &Bs[0][boff];
        bb[0]=w.x; bb[2]=w.y; bb[4]=w.z; bb[6]=w.w;
    }
    __syncthreads();

    int buf = 0;
    for (int kk = 16; kk <= K; kk += 16) {
        uint4 na, nw;
        bool more = (kk < K);
        if (more) {
            na = *(const uint4*)(Ag + kk);
            nw = wv ? *(const uint4*)(Wg + kk) : z4;
        }
        const uint32_t* Ab = As[buf];
        const uint32_t* Bb = Bs[buf];
        uint32_t af[4][4], bf[4][2];
        #pragma unroll
        for (int i = 0; i < 4; i++) {
            uint4 v = *(const uint4*)(Ab + (wm*4 + i)*128 + lane*4);
            af[i][0] = v.x; af[i][1] = v.y; af[i][2] = v.z; af[i][3] = v.w;
        }
        #pragma unroll
        for (int j = 0; j < 4; j++) {
            uint2 v = *(const uint2*)(Bb + (wn*4 + j)*64 + lane*2);
            bf[j][0] = v.x; bf[j][1] = v.y;
        }
        #pragma unroll
        for (int i = 0; i < 4; i++)
            #pragma unroll
            for (int j = 0; j < 4; j++)
                mma16(acc[i][j], af[i], bf[j]);
        if (more) {
            uint32_t* ab = &As[buf^1][aoff];
            ab[0]=na.x; ab[4]=na.y; ab[8]=na.z; ab[12]=na.w;
            uint32_t* bb = &Bs[buf^1][boff];
            bb[0]=nw.x; bb[2]=nw.y; bb[4]=nw.z; bb[6]=nw.w;
            __syncthreads();
            buf ^= 1;
        }
    }

    int r = lane >> 2, c2 = (lane & 3) * 2;
    #pragma unroll
    for (int i = 0; i < 4; i++) {
        int gr = row0 + wm*64 + i*16 + r;
        size_t rb0 = (size_t)gr * N;
        size_t rb1 = (size_t)(gr + 8) * N;
        #pragma unroll
        for (int j = 0; j < 4; j++) {
            int gc = col0 + wn*32 + j*8 + c2;
            const float* cp = acc[i][j];
            if (gc + 1 < N) {
                float b0 = bias[gc], b1 = bias[gc+1];
                float v0 = cp[0] + b0, v1 = cp[1] + b1;
                float v2 = cp[2] + b0, v3 = cp[3] + b1;
                if (epi == 0) {
                    C[rb0 + gc] = v0; C[rb0 + gc + 1] = v1;
                    C[rb1 + gc] = v2; C[rb1 + gc + 1] = v3;
                } else if (epi == 1) {
                    *(__half2*)(Ch + rb0 + gc) = __floats2half2_rn(gelu_f(v0), gelu_f(v1));
                    *(__half2*)(Ch + rb1 + gc) = __floats2half2_rn(gelu_f(v2), gelu_f(v3));
                } else {
                    v0 += res[rb0 + gc]; v1 += res[rb0 + gc + 1];
                    v2 += res[rb1 + gc]; v3 += res[rb1 + gc + 1];
                    C[rb0 + gc] = v0; C[rb0 + gc + 1] = v1;
                    C[rb1 + gc] = v2; C[rb1 + gc + 1] = v3;
                    if (epi == 3) {
                        *(__half2*)(Ch + rb0 + gc) = __floats2half2_rn(v0, v1);
                        *(__half2*)(Ch + rb1 + gc) = __floats2half2_rn(v2, v3);
                    }
                }
            } else if (gc < N) {
                float b0 = bias[gc];
                float v0 = cp[0] + b0, v2 = cp[2] + b0;
                if (epi == 0) {
                    C[rb0 + gc] = v0; C[rb1 + gc] = v2;
                } else if (epi == 1) {
                    Ch[rb0 + gc] = __float2half(gelu_f(v0));
                    Ch[rb1 + gc] = __float2half(gelu_f(v2));
                } else {
                    v0 += res[rb0 + gc]; v2 += res[rb1 + gc];
                    C[rb0 + gc] = v0; C[rb1 + gc] = v2;
                    if (epi == 3) {
                        Ch[rb0 + gc] = __float2half(v0);
                        Ch[rb1 + gc] = __float2half(v2);
                    }
                }
            }
        }
    }
}

__global__ void __launch_bounds__(256, 2) gemm_mma(const __half* __restrict__ A,
                                                   const __half* __restrict__ W,
                                                   const float* __restrict__ bias,
                                                   const float* __restrict__ res,
                                                   float* __restrict__ C,
                                                   __half* __restrict__ Ch,
                                                   int N, int K, int epi)
{
    gemm_mma_body(A, W, bias, res, C, Ch, N, K, blockIdx.y*128, blockIdx.x*128, epi);
}

__global__ void __launch_bounds__(256, 2) qktv_gemm(const __half* __restrict__ hn,
                                                    const __half* __restrict__ temb,
                                                    const __half* __restrict__ Wq, const __half* __restrict__ Wk,
                                                    const __half* __restrict__ Wt, const __half* __restrict__ Wv,
                                                    const float* __restrict__ bq, const float* __restrict__ bk,
                                                    const float* __restrict__ bt, const float* __restrict__ bv,
                                                    float* __restrict__ q, float* __restrict__ k1,
                                                    float* __restrict__ k2, float* __restrict__ v)
{
    int z = blockIdx.z;
    const __half* A = (z == 2) ? temb : hn;
    const __half* W = (z == 0) ? Wq : (z == 1) ? Wk : (z == 2) ? Wt : Wv;
    const float* b = (z == 0) ? bq : (z == 1) ? bk : (z == 2) ? bt : bv;
    float*       C = (z == 0) ? q  : (z == 1) ? k1 : (z == 2) ? k2 : v;
    gemm_mma_body(A, W, b, nullptr, C, nullptr, DD, DD, blockIdx.y*128, blockIdx.x*128, 0);
}

// ---------------- GEMM small: 64x64 tile, 4 warps (2Mx2N), warp 32x32, BK=16, double buffered ----
__global__ void __launch_bounds__(128) gemm_s(const __half* __restrict__ A,
                                              const __half* __restrict__ W,
                                              const float* __restrict__ bias,
                                              const float* __restrict__ res,
                                              float* __restrict__ C,
                                              __half* __restrict__ Ch,
                                              int N, int K, int epi)
{
    __shared__ uint32_t As[2][512];
    __shared__ uint32_t Bs[2][512];
    int tid = threadIdx.x;
    int warp = tid >> 5, lane = tid & 31;
    int wm = warp & 1, wn = warp >> 1;
    int row0 = blockIdx.y*64, col0 = blockIdx.x*64;

    float acc[2][4][4];
    #pragma unroll
    for (int i = 0; i < 2; i++)
        #pragma unroll
        for (int j = 0; j < 4; j++)
            #pragma unroll
            for (int q = 0; q < 4; q++) acc[i][j][q] = 0.f;

    int lrow = tid >> 1;          // 0..63
    int sK   = tid & 1;
    const __half* Ag = A + (size_t)(row0 + lrow)*K + sK*8;
    int wrow = col0 + lrow;
    const __half* Wg = W + (size_t)wrow*K + sK*8;
    bool wv = wrow < N;

    int t = lrow >> 4, rp = lrow & 15;        // t: 0..3
    int aoff = t*128 + (rp & 7)*16 + (rp >> 3) + sK*2;
    int u = lrow >> 3, np = lrow & 7;         // u: 0..7
    int boff = u*64 + np*8 + sK;
    const uint4 z4 = make_uint4(0u,0u,0u,0u);

    {
        uint4 a = *(const uint4*)(Ag);
        uint4 w = wv ? *(const uint4*)(Wg) : z4;
        uint32_t* ab = &As[0][aoff];
        ab[0]=a.x; ab[4]=a.y; ab[8]=a.z; ab[12]=a.w;
        uint32_t* bb = &Bs[0][boff];
        bb[0]=w.x; bb[2]=w.y; bb[4]=w.z; bb[6]=w.w;
    }
    __syncthreads();

    int buf = 0;
    for (int kk = 16; kk <= K; kk += 16) {
        uint4 na, nw;
        bool more = (kk < K);
        if (more) {
            na = *(const uint4*)(Ag + kk);
            nw = wv ? *(const uint4*)(Wg + kk) : z4;
        }
        const uint32_t* Ab = As[buf];
        const uint32_t* Bb = Bs[buf];
        uint32_t af[2][4], bf[4][2];
        #pragma unroll
        for (int i = 0; i < 2; i++) {
            uint4 v = *(const uint4*)(Ab + (wm*2 + i)*128 + lane*4);
            af[i][0] = v.x; af[i][1] = v.y; af[i][2] = v.z; af[i][3] = v.w;
        }
        #pragma unroll
        for (int j = 0; j < 4; j++) {
            uint2 v = *(const uint2*)(Bb + (wn*4 + j)*64 + lane*2);
            bf[j][0] = v.x; bf[j][1] = v.y;
        }
        #pragma unroll
        for (int i = 0; i < 2; i++)
            #pragma unroll
            for (int j = 0; j < 4; j++)
                mma16(acc[i][j], af[i], bf[j]);
        if (more) {
            uint32_t* ab = &As[buf^1][aoff];
            ab[0]=na.x; ab[4]=na.y; ab[8]=na.z; ab[12]=na.w;
            uint32_t* bb = &Bs[buf^1][boff];
            bb[0]=nw.x; bb[2]=nw.y; bb[4]=nw.z; bb[6]=nw.w;
            __syncthreads();
            buf ^= 1;
        }
    }

    int r = lane >> 2, c2 = (lane & 3) * 2;
    #pragma unroll
    for (int i = 0; i < 2; i++) {
        int gr = row0 + wm*32 + i*16 + r;
        size_t rb0 = (size_t)gr * N;
        size_t rb1 = (size_t)(gr + 8) * N;
        #pragma unroll
        for (int j = 0; j < 4; j++) {
            int gc = col0 + wn*32 + j*8 + c2;
            const float* cp = acc[i][j];
            if (gc + 1 < N) {
                float b0 = bias[gc], b1 = bias[gc+1];
                float v0 = cp[0] + b0, v1 = cp[1] + b1;
                float v2 = cp[2] + b0, v3 = cp[3] + b1;
                if (epi == 0) {
                    C[rb0 + gc] = v0; C[rb0 + gc + 1] = v1;
                    C[rb1 + gc] = v2; C[rb1 + gc + 1] = v3;
                } else if (epi == 1) {
                    *(__half2*)(Ch + rb0 + gc) = __floats2half2_rn(gelu_f(v0), gelu_f(v1));
                    *(__half2*)(Ch + rb1 + gc) = __floats2half2_rn(gelu_f(v2), gelu_f(v3));
                } else {
                    v0 += res[rb0 + gc]; v1 += res[rb0 + gc + 1];
                    v2 += res[rb1 + gc]; v3 += res[rb1 + gc + 1];
                    C[rb0 + gc] = v0; C[rb0 + gc + 1] = v1;
                    C[rb1 + gc] = v2; C[rb1 + gc + 1] = v3;
                    if (epi == 3) {
                        *(__half2*)(Ch + rb0 + gc) = __floats2half2_rn(v0, v1);
                        *(__half2*)(Ch + rb1 + gc) = __floats2half2_rn(v2, v3);
                    }
                }
            } else if (gc < N) {
                float b0 = bias[gc];
                float v0 = cp[0] + b0, v2 = cp[2] + b0;
                if (epi == 0) {
                    C[rb0 + gc] = v0; C[rb1 + gc] = v2;
                } else if (epi == 1) {
                    Ch[rb0 + gc] = __float2half(gelu_f(v0));
                    Ch[rb1 + gc] = __float2half(gelu_f(v2));
                } else {
                    v0 += res[rb0 + gc]; v2 += res[rb1 + gc];
                    C[rb0 + gc] = v0; C[rb1 + gc] = v2;
                    if (epi == 3) {
                        Ch[rb0 + gc] = __float2half(v0);
                        Ch[rb1 + gc] = __float2half(v2);
                    }
                }
            }
        }
    }
}

// ---------------- attention: grid (H, B, 2) -- fp32 K/V, ctx written as half ----------------
#define KTP 104

__global__ void __launch_bounds__(512) attn_kernel(
        const float* __restrict__ q, const float* __restrict__ k1,
        const float* __restrict__ k2, const float* __restrict__ v,
        const int* __restrict__ x, const float* __restrict__ ml,
        __half* __restrict__ ctx)
{
    extern __shared__ float sm[];
    float* qs  = sm;                    // SH*64
    float* vs  = qs  + SH*DK_;          // SS*64
    float* kct = vs  + SS*DK_;          // 64*KTP
    float* sc  = kct + DK_*KTP;         // SH*SS
    float* offs= sc + SH*SS;            // SS
    int h = blockIdx.x, b = blockIdx.y, z = blockIdx.z;
    int tid = threadIdx.x;
    int lane = tid & 31, warp = tid >> 5;
    int base = b*SS*DD + h*DK_;
    int q0 = z*SH;

    for (int idx = tid; idx < SS*DK_; idx += 512) {
        int s = idx >> 6, d = idx & 63;
        int gi = base + s*DD + d;
        vs[idx] = v[gi];
        bool kp = x[b*SS + s] > 0;
        float k2v = k2[gi];
        kct[d*KTP + s] = kp ? (k1[gi] + k2v) : k2v;
    }
    for (int idx = tid; idx < SH*DK_; idx += 512) {
        int s = idx >> 6, d = idx & 63;
        qs[idx] = q[base + (q0 + s)*DD + d];
    }
    if (tid < SS) offs[tid] = (x[b*SS + tid] > 0) ? 0.0f : -1e9f;
    __syncthreads();

    const float scale = 0.125f;
    for (int g = tid; g < SH*25; g += 512) {
        int qi = g / 25;
        int kg = (g - qi*25) * 4;
        const float* qp = qs + qi*DK_;
        float4 s1 = make_float4(0.f,0.f,0.f,0.f);
        #pragma unroll 8
        for (int d = 0; d < DK_; d++) {
            float qv = qp[d];
            float4 b1 = *(const float4*)(kct + d*KTP + kg);
            s1.x += qv*b1.x; s1.y += qv*b1.y; s1.z += qv*b1.z; s1.w += qv*b1.w;
        }
        float* sr = sc + qi*SS + kg;
        const float* op = offs + kg;
        sr[0] = s1.x*scale + op[0];
        sr[1] = s1.y*scale + op[1];
        sr[2] = s1.z*scale + op[2];
        sr[3] = s1.w*scale + op[3];
    }
    __syncthreads();

    for (int r = warp; r < SH; r += 16) {
        float* row = sc + r*SS;
        float mx = -1e30f;
        for (int c = lane; c < SS; c += 32) mx = fmaxf(mx, row[c]);
        #pragma unroll
        for (int o = 16; o > 0; o >>= 1) mx = fmaxf(mx, __shfl_xor_sync(0xffffffff, mx, o));
        float sum = 0.f;
        for (int c = lane; c < SS; c += 32) {
            float e = __expf(row[c] - mx);
            row[c] = e; sum += e;
        }
        #pragma unroll
        for (int o = 16; o > 0; o >>= 1) sum += __shfl_xor_sync(0xffffffff, sum, o);
        float inv = 1.0f / sum;
        const float* mlr = ml + (q0 + r)*SS;
        for (int c = lane; c < SS; c += 32) {
            float zz = mlr[c];
            float sg = 1.0f / (1.0f + __expf(-zz));
            row[c] *= inv * sg;
        }
    }
    __syncthreads();

    for (int o = tid; o < SH*16; o += 512) {
        int qi = o >> 4;
        int dg = (o & 15) * 4;
        const float* sr = sc + qi*SS;
        const float* vp = vs + dg;
        float4 a = make_float4(0.f,0.f,0.f,0.f);
        #pragma unroll 4
        for (int k = 0; k < SS; k++) {
            float p = sr[k];
            float4 vv = *(const float4*)(vp + k*DK_);
            a.x += p*vv.x; a.y += p*vv.y; a.z += p*vv.z; a.w += p*vv.w;
        }
        __half2* dst = (__half2*)(ctx + base + (q0 + qi)*DD + dg);
        dst[0] = __floats2half2_rn(a.x, a.y);
        dst[1] = __floats2half2_rn(a.z, a.w);
    }
}

// ---------------- host launcher ----------------
extern "C" void kernel_launch(void* const* d_in, const int* in_sizes, int n_in,
                              void* d_out, int out_size)
{
    (void)in_sizes; (void)n_in; (void)out_size;
    const int*   x         = (const int*)  d_in[0];
    const float* times     = (const float*)d_in[1];
    const float* token_emb = (const float*)d_in[2];
    const float* pos_emb   = (const float*)d_in[3];
    const float* sel_w     = (const float*)d_in[4];
    const float* sel_b     = (const float*)d_in[5];
    const float* time_w    = (const float*)d_in[6];
    const float* time_b    = (const float*)d_in[7];
    const float* per_w     = (const float*)d_in[8];
    const float* per_b     = (const float*)d_in[9];
    const float* Wq        = (const float*)d_in[10];
    const float* Wk        = (const float*)d_in[11];
    const float* Wt        = (const float*)d_in[12];
    const float* Wv        = (const float*)d_in[13];
    const float* Wo        = (const float*)d_in[14];
    const float* bq        = (const float*)d_in[15];
    const float* bk        = (const float*)d_in[16];
    const float* bt        = (const float*)d_in[17];
    const float* bv        = (const float*)d_in[18];
    const float* bo        = (const float*)d_in[19];
    const float* mask_log  = (const float*)d_in[20];
    const float* ln1_a     = (const float*)d_in[21];
    const float* ln1_b     = (const float*)d_in[22];
    const float* ln2_a     = (const float*)d_in[23];
    const float* ln2_b     = (const float*)d_in[24];
    const float* ffn_w1    = (const float*)d_in[25];
    const float* ffn_b1    = (const float*)d_in[26];
    const float* ffn_w2    = (const float*)d_in[27];
    const float* ffn_b2    = (const float*)d_in[28];
    const float* out_w     = (const float*)d_in[29];
    const float* out_b     = (const float*)d_in[30];
    float* out = (float*)d_out;

    float *ph,*pq,*pk1,*pk2,*pv;
    __half *phn,*ptemb,*pctx,*pffn,*phh;
    __half *wq,*wk,*wt,*wv_,*wo,*w1,*w2,*wout;
    cudaGetSymbolAddress((void**)&ph,    g_h);
    cudaGetSymbolAddress((void**)&pq,    g_q);
    cudaGetSymbolAddress((void**)&pk1,   g_k1);
    cudaGetSymbolAddress((void**)&pk2,   g_k2);
    cudaGetSymbolAddress((void**)&pv,    g_v);
    cudaGetSymbolAddress((void**)&phn,   g_hn_h);
    cudaGetSymbolAddress((void**)&ptemb, g_temb_h);
    cudaGetSymbolAddress((void**)&pctx,  g_ctx_h);
    cudaGetSymbolAddress((void**)&pffn,  g_ffn_h);
    cudaGetSymbolAddress((void**)&phh,   g_hh);
    cudaGetSymbolAddress((void**)&wq,    g_Wqh);
    cudaGetSymbolAddress((void**)&wk,    g_Wkh);
    cudaGetSymbolAddress((void**)&wt,    g_Wth);
    cudaGetSymbolAddress((void**)&wv_,   g_Wvh);
    cudaGetSymbolAddress((void**)&wo,    g_Woh);
    cudaGetSymbolAddress((void**)&w1,    g_w1h);
    cudaGetSymbolAddress((void**)&w2,    g_w2h);
    cudaGetSymbolAddress((void**)&wout,  g_outwh);

    const int attn_smem = (SH*DK_ + SS*DK_ + DK_*KTP + SH*SS + SS)*(int)sizeof(float); // ~85.4 KB
    cudaFuncSetAttribute(attn_kernel, cudaFuncAttributeMaxDynamicSharedMemorySize, attn_smem);

    // weight conversion: 2 launches (7 small tensors batched + the big out_w)
    const int n7 = 5*(LL*DD*DD/4) + 2*(LL*DFF_*DD/4);   // 638,976
    const int nOut = NOUT*DD/4;
    f2h7_kernel<<<(n7+255)/256, 256>>>(Wq, Wk, Wt, Wv, Wo, ffn_w1, ffn_w2,
                                       wq, wk, wt, wv_, wo, w1, w2);
    f2h_kernel<<<(nOut+255)/256, 256>>>(out_w, wout, nOut);

    embed_kernel<<<MM, 256>>>(x, times, token_emb, pos_emb, sel_w, sel_b,
                              time_w, time_b, per_w, per_b);

    dim3 gF(8, 25);            // 128x128 tiles, N=1024
    dim3 gS(4, 50);            // 64x64 tiles, N=256
    dim3 gQKTV(2, 25, 4);
    for (int l = 0; l < LL; l++) {
        ln_kernel<<<MM, 256>>>(ph, ln1_a + l*DD, ln1_b + l*DD, phn);
        qktv_gemm<<<gQKTV, 256>>>(phn, ptemb,
                                  wq + (size_t)l*DD*DD, wk + (size_t)l*DD*DD,
                                  wt + (size_t)l*DD*DD, wv_ + (size_t)l*DD*DD,
                                  bq + l*DD, bk + l*DD, bt + l*DD, bv + l*DD,
                                  pq, pk1, pk2, pv);
        attn_kernel<<<dim3(HH, BB, 2), 512, attn_smem>>>(pq, pk1, pk2, pv, x,
                                                         mask_log + l*SS*SS, pctx);
        gemm_s<<<gS, 128>>>(pctx, wo + (size_t)l*DD*DD, bo + l*DD, ph, ph, nullptr, DD, DD, 2);
        ln_kernel<<<MM, 256>>>(ph, ln2_a + l*DD, ln2_b + l*DD, phn);
        gemm_mma<<<gF, 256>>>(phn, w1 + (size_t)l*DFF_*DD, ffn_b1 + l*DFF_,
                              nullptr, nullptr, pffn, DFF_, DD, 1);
        gemm_s<<<gS, 128>>>(pffn, w2 + (size_t)l*DD*DFF_, ffn_b2 + l*DD, ph, ph, phh, DD, DFF_, 3);
    }
    gemm_mma<<<dim3(391, 25), 256>>>(phh, wout, out_b, nullptr, out, nullptr, NOUT, DD, 0);
}

// round 16
// speedup vs baseline: 1.1128x; 1.0377x over previous
#include <cuda_runtime.h>
#include <cuda_fp16.h>
#include <math.h>
#include <stdint.h>

// Problem constants
#define BB   32
#define SS   100
#define SH   50        // q rows per attention block (split 2)
#define DD   256
#define HH   4
#define DK_  64
#define LL   3
#define MM   (BB*SS)      // 3200
#define DFF_ 1024
#define NOUT 50001

// ---------------- scratch (no allocation allowed -> device globals) ----------------
__device__ float g_h[MM*DD];
__device__ float g_q[MM*DD];
// fp16 operand network
__device__ __align__(16) __half g_k1h[MM*DD];
__device__ __align__(16) __half g_k2h[MM*DD];
__device__ __align__(16) __half g_vh[MM*DD];
__device__ __align__(16) __half g_hn_h[MM*DD];
__device__ __align__(16) __half g_temb_h[MM*DD];
__device__ __align__(16) __half g_ctx_h[MM*DD];
__device__ __align__(16) __half g_ffn_h[MM*DFF_];
__device__ __align__(16) __half g_hh[MM*DD];
// fp16 weights
__device__ __align__(16) __half g_Wqh[LL*DD*DD];
__device__ __align__(16) __half g_Wkh[LL*DD*DD];
__device__ __align__(16) __half g_Wth[LL*DD*DD];
__device__ __align__(16) __half g_Wvh[LL*DD*DD];
__device__ __align__(16) __half g_Woh[LL*DD*DD];
__device__ __align__(16) __half g_w1h[LL*DFF_*DD];
__device__ __align__(16) __half g_w2h[LL*DD*DFF_];
__device__ __align__(16) __half g_outwh[(size_t)NOUT*DD];

// ---------------- fp32 -> fp16 convert ----------------
__global__ void f2h_kernel(const float* __restrict__ src, __half* __restrict__ dst, int n4) {
    int i = blockIdx.x*blockDim.x + threadIdx.x;
    if (i < n4) {
        float4 v = ((const float4*)src)[i];
        ((__half2*)dst)[i*2]   = __floats2half2_rn(v.x, v.y);
        ((__half2*)dst)[i*2+1] = __floats2half2_rn(v.z, v.w);
    }
}

// one launch converts the 7 layer-weight tensors
__global__ void f2h7_kernel(const float* __restrict__ Wq, const float* __restrict__ Wk,
                            const float* __restrict__ Wt, const float* __restrict__ Wv,
                            const float* __restrict__ Wo, const float* __restrict__ w1f,
                            const float* __restrict__ w2f,
                            __half* __restrict__ wq, __half* __restrict__ wk,
                            __half* __restrict__ wt, __half* __restrict__ wv,
                            __half* __restrict__ wo, __half* __restrict__ w1,
                            __half* __restrict__ w2)
{
    const int nD  = LL*DD*DD/4;      // 49152
    const int nFF = LL*DFF_*DD/4;    // 196608
    int i = blockIdx.x*blockDim.x + threadIdx.x;
    const float* s; __half* d; int off;
    if (i < 5*nD) {
        int seg = i / nD; off = i - seg*nD;
        s = (seg==0)?Wq:(seg==1)?Wk:(seg==2)?Wt:(seg==3)?Wv:Wo;
        d = (seg==0)?wq:(seg==1)?wk:(seg==2)?wt:(seg==3)?wv:wo;
    } else {
        int j = i - 5*nD;
        if (j >= 2*nFF) return;
        int seg = j / nFF; off = j - seg*nFF;
        s = seg ? w2f : w1f;
        d = seg ? w2  : w1;
    }
    float4 v = ((const float4*)s)[off];
    ((__half2*)d)[off*2]   = __floats2half2_rn(v.x, v.y);
    ((__half2*)d)[off*2+1] = __floats2half2_rn(v.z, v.w);
}

// ---------------- embedding + time embedding ----------------
__global__ void embed_kernel(const int* __restrict__ x, const float* __restrict__ times,
                             const float* __restrict__ token_emb, const float* __restrict__ pos_emb,
                             const float* __restrict__ sel_w, const float* __restrict__ sel_b,
                             const float* __restrict__ time_w, const float* __restrict__ time_b,
                             const float* __restrict__ per_w, const float* __restrict__ per_b)
{
    int bs = blockIdx.x;
    int s  = bs % SS;
    int d  = threadIdx.x;
    __shared__ float g[64];
    float tval = times[bs];
    if (d < 64) {
        float t = tval * (1.0f/180.0f) * sel_w[d] + sel_b[d];
        g[d] = 1.0f - tanhf(t*t);
    }
    __syncthreads();
    float ang = 2.0f * 3.14159265358979323846f * tval / 24.0f;
    float sa = sinf(ang), ca = cosf(ang);
    float feat = time_b[d];
    const float* tw = time_w + d*64;
    #pragma unroll 16
    for (int j = 0; j < 64; j++) feat += g[j] * tw[j];
    float per = sa*per_w[d*2+0] + ca*per_w[d*2+1] + per_b[d];
    g_temb_h[bs*DD + d] = __float2half(feat + per);
    int tok = x[bs];
    g_h[bs*DD + d] = token_emb[(size_t)tok*DD + d] + pos_emb[s*DD + d];
}

// ---------------- LayerNorm (torch variant) -> half output ----------------
__global__ void ln_kernel(const float* __restrict__ x, const float* __restrict__ a,
                          const float* __restrict__ b, __half* __restrict__ y)
{
    int row = blockIdx.x;
    int d = threadIdx.x;
    int lane = d & 31, warp = d >> 5;
    __shared__ float ws1[8], ws2[8];
    float v = x[row*DD + d];
    float s = v;
    #pragma unroll
    for (int o = 16; o > 0; o >>= 1) s += __shfl_xor_sync(0xffffffff, s, o);
    if (lane == 0) ws1[warp] = s;
    __syncthreads();
    float tot = 0.f;
    #pragma unroll
    for (int i = 0; i < 8; i++) tot += ws1[i];
    float mean = tot * (1.0f/DD);
    float diff = v - mean;
    float s2 = diff*diff;
    #pragma unroll
    for (int o = 16; o > 0; o >>= 1) s2 += __shfl_xor_sync(0xffffffff, s2, o);
    if (lane == 0) ws2[warp] = s2;
    __syncthreads();
    float tot2 = 0.f;
    #pragma unroll
    for (int i = 0; i < 8; i++) tot2 += ws2[i];
    float stdv = sqrtf(tot2 * (1.0f/(DD-1)));
    y[row*DD + d] = __float2half(a[d]*diff/(stdv + 1e-6f) + b[d]);
}

// ---------------- GELU ----------------
__device__ __forceinline__ float gelu_f(float x) {
    const float c = 0.7978845608028654f;   // sqrt(2/pi)
    float x3 = x*x*x;
    return 0.5f*x*(1.0f + tanhf(c*(x + 0.044715f*x3)));
}

// ---------------- raw mma.m16n8k16 fp16 (fp32 accum) ----------------
__device__ __forceinline__ void mma16(float* c, const uint32_t* a, const uint32_t* b) {
    asm volatile("mma.sync.aligned.m16n8k16.row.col.f32.f16.f16.f32 "
        "{%0,%1,%2,%3}, {%4,%5,%6,%7}, {%8,%9}, {%0,%1,%2,%3};"
        : "+f"(c[0]), "+f"(c[1]), "+f"(c[2]), "+f"(c[3])
        : "r"(a[0]), "r"(a[1]), "r"(a[2]), "r"(a[3]), "r"(b[0]), "r"(b[1]));
}

// ---------------- GEMM v1: 128x128 tile, 8 warps (2Mx4N), warp 64x32, BK=16, double buffered ----
// epi: 0 = C fp32; 1 = Ch = half(gelu); 2 = C fp32 += res; 3 = C += res AND Ch = half(C); 4 = Ch = half
__device__ __forceinline__ void gemm_mma_body(const __half* __restrict__ A,
                                              const __half* __restrict__ W,
                                              const float* __restrict__ bias,
                                              const float* __restrict__ res,
                                              float* __restrict__ C,
                                              __half* __restrict__ Ch,
                                              int N, int K, int row0, int col0, int epi)
{
    __shared__ uint32_t As[2][1024];
    __shared__ uint32_t Bs[2][1024];
    int tid = threadIdx.x;
    int warp = tid >> 5, lane = tid & 31;
    int wm = warp & 1, wn = warp >> 1;

    float acc[4][4][4];
    #pragma unroll
    for (int i = 0; i < 4; i++)
        #pragma unroll
        for (int j = 0; j < 4; j++)
            #pragma unroll
            for (int q = 0; q < 4; q++) acc[i][j][q] = 0.f;

    int lrow = tid >> 1;
    int sK   = tid & 1;
    const __half* Ag = A + (size_t)(row0 + lrow)*K + sK*8;
    int wrow = col0 + lrow;
    const __half* Wg = W + (size_t)wrow*K + sK*8;
    bool wv = wrow < N;

    int t = lrow >> 4, rp = lrow & 15;
    int aoff = t*128 + (rp & 7)*16 + (rp >> 3) + sK*2;
    int u = lrow >> 3, np = lrow & 7;
    int boff = u*64 + np*8 + sK;
    const uint4 z4 = make_uint4(0u,0u,0u,0u);

    {
        uint4 a = *(const uint4*)(Ag);
        uint4 w = wv ? *(const uint4*)(Wg) : z4;
        uint32_t* ab = &As[0][aoff];
        ab[0]=a.x; ab[4]=a.y; ab[8]=a.z; ab[12]=a.w;
        uint32_t* bb = &Bs[0][boff];
        bb[0]=w.x; bb[2]=w.y; bb[4]=w.z; bb[6]=w.w;
    }
    __syncthreads();

    int buf = 0;
    for (int kk = 16; kk <= K; kk += 16) {
        uint4 na, nw;
        bool more = (kk < K);
        if (more) {
            na = *(const uint4*)(Ag + kk);
            nw = wv ? *(const uint4*)(Wg + kk) : z4;
        }
        const uint32_t* Ab = As[buf];
        const uint32_t* Bb = Bs[buf];
        uint32_t af[4][4], bf[4][2];
        #pragma unroll
        for (int i = 0; i < 4; i++) {
            uint4 v = *(const uint4*)(Ab + (wm*4 + i)*128 + lane*4);
            af[i][0] = v.x; af[i][1] = v.y; af[i][2] = v.z; af[i][3] = v.w;
        }
        #pragma unroll
        for (int j = 0; j < 4; j++) {
            uint2 v = *(const uint2*)(Bb + (wn*4 + j)*64 + lane*2);
            bf[j][0] = v.x; bf[j][1] = v.y;
        }
        #pragma unroll
        for (int i = 0; i < 4; i++)
            #pragma unroll
            for (int j = 0; j < 4; j++)
                mma16(acc[i][j], af[i], bf[j]);
        if (more) {
            uint32_t* ab = &As[buf^1][aoff];
            ab[0]=na.x; ab[4]=na.y; ab[8]=na.z; ab[12]=na.w;
            uint32_t* bb = &Bs[buf^1][boff];
            bb[0]=nw.x; bb[2]=nw.y; bb[4]=nw.z; bb[6]=nw.w;
            __syncthreads();
            buf ^= 1;
        }
    }

    int r = lane >> 2, c2 = (lane & 3) * 2;
    #pragma unroll
    for (int i = 0; i < 4; i++) {
        int gr = row0 + wm*64 + i*16 + r;
        size_t rb0 = (size_t)gr * N;
        size_t rb1 = (size_t)(gr + 8) * N;
        #pragma unroll
        for (int j = 0; j < 4; j++) {
            int gc = col0 + wn*32 + j*8 + c2;
            const float* cp = acc[i][j];
            if (gc + 1 < N) {
                float b0 = bias[gc], b1 = bias[gc+1];
                float v0 = cp[0] + b0, v1 = cp[1] + b1;
                float v2 = cp[2] + b0, v3 = cp[3] + b1;
                if (epi == 0) {
                    C[rb0 + gc] = v0; C[rb0 + gc + 1] = v1;
                    C[rb1 + gc] = v2; C[rb1 + gc + 1] = v3;
                } else if (epi == 1) {
                    *(__half2*)(Ch + rb0 + gc) = __floats2half2_rn(gelu_f(v0), gelu_f(v1));
                    *(__half2*)(Ch + rb1 + gc) = __floats2half2_rn(gelu_f(v2), gelu_f(v3));
                } else if (epi == 4) {
                    *(__half2*)(Ch + rb0 + gc) = __floats2half2_rn(v0, v1);
                    *(__half2*)(Ch + rb1 + gc) = __floats2half2_rn(v2, v3);
                } else {
                    v0 += res[rb0 + gc]; v1 += res[rb0 + gc + 1];
                    v2 += res[rb1 + gc]; v3 += res[rb1 + gc + 1];
                    C[rb0 + gc] = v0; C[rb0 + gc + 1] = v1;
                    C[rb1 + gc] = v2; C[rb1 + gc + 1] = v3;
                    if (epi == 3) {
                        *(__half2*)(Ch + rb0 + gc) = __floats2half2_rn(v0, v1);
                        *(__half2*)(Ch + rb1 + gc) = __floats2half2_rn(v2, v3);
                    }
                }
            } else if (gc < N) {
                float b0 = bias[gc];
                float v0 = cp[0] + b0, v2 = cp[2] + b0;
                if (epi == 0) {
                    C[rb0 + gc] = v0; C[rb1 + gc] = v2;
                } else if (epi == 1) {
                    Ch[rb0 + gc] = __float2half(gelu_f(v0));
                    Ch[rb1 + gc] = __float2half(gelu_f(v2));
                } else if (epi == 4) {
                    Ch[rb0 + gc] = __float2half(v0);
                    Ch[rb1 + gc] = __float2half(v2);
                } else {
                    v0 += res[rb0 + gc]; v2 += res[rb1 + gc];
                    C[rb0 + gc] = v0; C[rb1 + gc] = v2;
                    if (epi == 3) {
                        Ch[rb0 + gc] = __float2half(v0);
                        Ch[rb1 + gc] = __float2half(v2);
                    }
                }
            }
        }
    }
}

__global__ void __launch_bounds__(256, 2) gemm_mma(const __half* __restrict__ A,
                                                   const __half* __restrict__ W,
                                                   const float* __restrict__ bias,
                                                   const float* __restrict__ res,
                                                   float* __restrict__ C,
                                                   __half* __restrict__ Ch,
                                                   int N, int K, int epi)
{
    gemm_mma_body(A, W, bias, res, C, Ch, N, K, blockIdx.y*128, blockIdx.x*128, epi);
}

__global__ void __launch_bounds__(256, 2) qktv_gemm(const __half* __restrict__ hn,
                                                    const __half* __restrict__ temb,
                                                    const __half* __restrict__ Wq, const __half* __restrict__ Wk,
                                                    const __half* __restrict__ Wt, const __half* __restrict__ Wv,
                                                    const float* __restrict__ bq, const float* __restrict__ bk,
                                                    const float* __restrict__ bt, const float* __restrict__ bv,
                                                    float* __restrict__ q, __half* __restrict__ k1,
                                                    __half* __restrict__ k2, __half* __restrict__ v)
{
    int z = blockIdx.z;
    const __half* A = (z == 2) ? temb : hn;
    const __half* W = (z == 0) ? Wq : (z == 1) ? Wk : (z == 2) ? Wt : Wv;
    const float* b = (z == 0) ? bq : (z == 1) ? bk : (z == 2) ? bt : bv;
    if (z == 0)
        gemm_mma_body(A, W, b, nullptr, q, nullptr, DD, DD, blockIdx.y*128, blockIdx.x*128, 0);
    else {
        __half* Ch = (z == 1) ? k1 : (z == 2) ? k2 : v;
        gemm_mma_body(A, W, b, nullptr, nullptr, Ch, DD, DD, blockIdx.y*128, blockIdx.x*128, 4);
    }
}

// ---------------- GEMM small: 64x64 tile, 4 warps (2Mx2N), warp 32x32, BK=16, double buffered ----
__global__ void __launch_bounds__(128) gemm_s(const __half* __restrict__ A,
                                              const __half* __restrict__ W,
                                              const float* __restrict__ bias,
                                              const float* __restrict__ res,
                                              float* __restrict__ C,
                                              __half* __restrict__ Ch,
                                              int N, int K, int epi)
{
    __shared__ uint32_t As[2][512];
    __shared__ uint32_t Bs[2][512];
    int tid = threadIdx.x;
    int warp = tid >> 5, lane = tid & 31;
    int wm = warp & 1, wn = warp >> 1;
    int row0 = blockIdx.y*64, col0 = blockIdx.x*64;

    float acc[2][4][4];
    #pragma unroll
    for (int i = 0; i < 2; i++)
        #pragma unroll
        for (int j = 0; j < 4; j++)
            #pragma unroll
            for (int q = 0; q < 4; q++) acc[i][j][q] = 0.f;

    int lrow = tid >> 1;          // 0..63
    int sK   = tid & 1;
    const __half* Ag = A + (size_t)(row0 + lrow)*K + sK*8;
    int wrow = col0 + lrow;
    const __half* Wg = W + (size_t)wrow*K + sK*8;
    bool wv = wrow < N;

    int t = lrow >> 4, rp = lrow & 15;        // t: 0..3
    int aoff = t*128 + (rp & 7)*16 + (rp >> 3) + sK*2;
    int u = lrow >> 3, np = lrow & 7;         // u: 0..7
    int boff = u*64 + np*8 + sK;
    const uint4 z4 = make_uint4(0u,0u,0u,0u);

    {
        uint4 a = *(const uint4*)(Ag);
        uint4 w = wv ? *(const uint4*)(Wg) : z4;
        uint32_t* ab = &As[0][aoff];
        ab[0]=a.x; ab[4]=a.y; ab[8]=a.z; ab[12]=a.w;
        uint32_t* bb = &Bs[0][boff];
        bb[0]=w.x; bb[2]=w.y; bb[4]=w.z; bb[6]=w.w;
    }
    __syncthreads();

    int buf = 0;
    for (int kk = 16; kk <= K; kk += 16) {
        uint4 na, nw;
        bool more = (kk < K);
        if (more) {
            na = *(const uint4*)(Ag + kk);
            nw = wv ? *(const uint4*)(Wg + kk) : z4;
        }
        const uint32_t* Ab = As[buf];
        const uint32_t* Bb = Bs[buf];
        uint32_t af[2][4], bf[4][2];
        #pragma unroll
        for (int i = 0; i < 2; i++) {
            uint4 v = *(const uint4*)(Ab + (wm*2 + i)*128 + lane*4);
            af[i][0] = v.x; af[i][1] = v.y; af[i][2] = v.z; af[i][3] = v.w;
        }
        #pragma unroll
        for (int j = 0; j < 4; j++) {
            uint2 v = *(const uint2*)(Bb + (wn*4 + j)*64 + lane*2);
            bf[j][0] = v.x; bf[j][1] = v.y;
        }
        #pragma unroll
        for (int i = 0; i < 2; i++)
            #pragma unroll
            for (int j = 0; j < 4; j++)
                mma16(acc[i][j], af[i], bf[j]);
        if (more) {
            uint32_t* ab = &As[buf^1][aoff];
            ab[0]=na.x; ab[4]=na.y; ab[8]=na.z; ab[12]=na.w;
            uint32_t* bb = &Bs[buf^1][boff];
            bb[0]=nw.x; bb[2]=nw.y; bb[4]=nw.z; bb[6]=nw.w;
            __syncthreads();
            buf ^= 1;
        }
    }

    int r = lane >> 2, c2 = (lane & 3) * 2;
    #pragma unroll
    for (int i = 0; i < 2; i++) {
        int gr = row0 + wm*32 + i*16 + r;
        size_t rb0 = (size_t)gr * N;
        size_t rb1 = (size_t)(gr + 8) * N;
        #pragma unroll
        for (int j = 0; j < 4; j++) {
            int gc = col0 + wn*32 + j*8 + c2;
            const float* cp = acc[i][j];
            if (gc + 1 < N) {
                float b0 = bias[gc], b1 = bias[gc+1];
                float v0 = cp[0] + b0, v1 = cp[1] + b1;
                float v2 = cp[2] + b0, v3 = cp[3] + b1;
                if (epi == 0) {
                    C[rb0 + gc] = v0; C[rb0 + gc + 1] = v1;
                    C[rb1 + gc] = v2; C[rb1 + gc + 1] = v3;
                } else if (epi == 1) {
                    *(__half2*)(Ch + rb0 + gc) = __floats2half2_rn(gelu_f(v0), gelu_f(v1));
                    *(__half2*)(Ch + rb1 + gc) = __floats2half2_rn(gelu_f(v2), gelu_f(v3));
                } else {
                    v0 += res[rb0 + gc]; v1 += res[rb0 + gc + 1];
                    v2 += res[rb1 + gc]; v3 += res[rb1 + gc + 1];
                    C[rb0 + gc] = v0; C[rb0 + gc + 1] = v1;
                    C[rb1 + gc] = v2; C[rb1 + gc + 1] = v3;
                    if (epi == 3) {
                        *(__half2*)(Ch + rb0 + gc) = __floats2half2_rn(v0, v1);
                        *(__half2*)(Ch + rb1 + gc) = __floats2half2_rn(v2, v3);
                    }
                }
            } else if (gc < N) {
                float b0 = bias[gc];
                float v0 = cp[0] + b0, v2 = cp[2] + b0;
                if (epi == 0) {
                    C[rb0 + gc] = v0; C[rb1 + gc] = v2;
                } else if (epi == 1) {
                    Ch[rb0 + gc] = __float2half(gelu_f(v0));
                    Ch[rb1 + gc] = __float2half(gelu_f(v2));
                } else {
                    v0 += res[rb0 + gc]; v2 += res[rb1 + gc];
                    C[rb0 + gc] = v0; C[rb1 + gc] = v2;
                    if (epi == 3) {
                        Ch[rb0 + gc] = __float2half(v0);
                        Ch[rb1 + gc] = __float2half(v2);
                    }
                }
            }
        }
    }
}

// ---------------- attention: grid (H, B, 2), half K/V, fp32 q + accum ----------------
#define KTP 104

__global__ void __launch_bounds__(512) attn_kernel(
        const float* __restrict__ q, const __half* __restrict__ k1,
        const __half* __restrict__ k2, const __half* __restrict__ v,
        const int* __restrict__ x, const float* __restrict__ ml,
        __half* __restrict__ ctx)
{
    extern __shared__ char smbase[];
    float*  qs  = (float*)smbase;                       // SH*64 f32
    __half* vs  = (__half*)(smbase + SH*DK_*4);         // SS*64 half
    __half* kct = (__half*)(smbase + SH*DK_*4 + SS*DK_*2);   // 64*KTP half
    float*  sc  = (float*)(smbase + SH*DK_*4 + SS*DK_*2 + DK_*KTP*2);  // SH*SS f32
    float*  offs= sc + SH*SS;                           // SS f32
    int h = blockIdx.x, b = blockIdx.y, z = blockIdx.z;
    int tid = threadIdx.x;
    int lane = tid & 31, warp = tid >> 5;
    int base = b*SS*DD + h*DK_;
    int q0 = z*SH;

    for (int idx = tid; idx < SS*DK_; idx += 512) {
        int s = idx >> 6, d = idx & 63;
        int gi = base + s*DD + d;
        vs[idx] = v[gi];
        bool kp = x[b*SS + s] > 0;
        float k2v = __half2float(k2[gi]);
        float kv = kp ? (__half2float(k1[gi]) + k2v) : k2v;
        kct[d*KTP + s] = __float2half(kv);
    }
    for (int idx = tid; idx < SH*DK_; idx += 512) {
        int s = idx >> 6, d = idx & 63;
        qs[idx] = q[base + (q0 + s)*DD + d];
    }
    if (tid < SS) offs[tid] = (x[b*SS + tid] > 0) ? 0.0f : -1e9f;
    __syncthreads();

    const float scale = 0.125f;
    for (int g = tid; g < SH*25; g += 512) {
        int qi = g / 25;
        int kg = (g - qi*25) * 4;
        const float* qp = qs + qi*DK_;
        float4 s1 = make_float4(0.f,0.f,0.f,0.f);
        #pragma unroll 8
        for (int d = 0; d < DK_; d++) {
            float qv = qp[d];
            const __half2* kp2 = (const __half2*)(kct + d*KTP + kg);
            float2 f0 = __half22float2(kp2[0]);
            float2 f1 = __half22float2(kp2[1]);
            s1.x += qv*f0.x; s1.y += qv*f0.y; s1.z += qv*f1.x; s1.w += qv*f1.y;
        }
        float* sr = sc + qi*SS + kg;
        const float* op = offs + kg;
        sr[0] = s1.x*scale + op[0];
        sr[1] = s1.y*scale + op[1];
        sr[2] = s1.z*scale + op[2];
        sr[3] = s1.w*scale + op[3];
    }
    __syncthreads();

    for (int r = warp; r < SH; r += 16) {
        float* row = sc + r*SS;
        float mx = -1e30f;
        for (int c = lane; c < SS; c += 32) mx = fmaxf(mx, row[c]);
        #pragma unroll
        for (int o = 16; o > 0; o >>= 1) mx = fmaxf(mx, __shfl_xor_sync(0xffffffff, mx, o));
        float sum = 0.f;
        for (int c = lane; c < SS; c += 32) {
            float e = __expf(row[c] - mx);
            row[c] = e; sum += e;
        }
        #pragma unroll
        for (int o = 16; o > 0; o >>= 1) sum += __shfl_xor_sync(0xffffffff, sum, o);
        float inv = 1.0f / sum;
        const float* mlr = ml + (q0 + r)*SS;
        for (int c = lane; c < SS; c += 32) {
            float zz = mlr[c];
            float sg = 1.0f / (1.0f + __expf(-zz));
            row[c] *= inv * sg;
        }
    }
    __syncthreads();

    for (int o = tid; o < SH*16; o += 512) {
        int qi = o >> 4;
        int dg = (o & 15) * 4;
        const float* sr = sc + qi*SS;
        const __half* vp = vs + dg;
        float4 a = make_float4(0.f,0.f,0.f,0.f);
        #pragma unroll 4
        for (int k = 0; k < SS; k++) {
            float p = sr[k];
            const __half2* v2p = (const __half2*)(vp + k*DK_);
            float2 f0 = __half22float2(v2p[0]);
            float2 f1 = __half22float2(v2p[1]);
            a.x += p*f0.x; a.y += p*f0.y; a.z += p*f1.x; a.w += p*f1.y;
        }
        __half2* dst = (__half2*)(ctx + base + (q0 + qi)*DD + dg);
        dst[0] = __floats2half2_rn(a.x, a.y);
        dst[1] = __floats2half2_rn(a.z, a.w);
    }
}

// ---------------- host launcher ----------------
extern "C" void kernel_launch(void* const* d_in, const int* in_sizes, int n_in,
                              void* d_out, int out_size)
{
    (void)in_sizes; (void)n_in; (void)out_size;
    const int*   x         = (const int*)  d_in[0];
    const float* times     = (const float*)d_in[1];
    const float* token_emb = (const float*)d_in[2];
    const float* pos_emb   = (const float*)d_in[3];
    const float* sel_w     = (const float*)d_in[4];
    const float* sel_b     = (const float*)d_in[5];
    const float* time_w    = (const float*)d_in[6];
    const float* time_b    = (const float*)d_in[7];
    const float* per_w     = (const float*)d_in[8];
    const float* per_b     = (const float*)d_in[9];
    const float* Wq        = (const float*)d_in[10];
    const float* Wk        = (const float*)d_in[11];
    const float* Wt        = (const float*)d_in[12];
    const float* Wv        = (const float*)d_in[13];
    const float* Wo        = (const float*)d_in[14];
    const float* bq        = (const float*)d_in[15];
    const float* bk        = (const float*)d_in[16];
    const float* bt        = (const float*)d_in[17];
    const float* bv        = (const float*)d_in[18];
    const float* bo        = (const float*)d_in[19];
    const float* mask_log  = (const float*)d_in[20];
    const float* ln1_a     = (const float*)d_in[21];
    const float* ln1_b     = (const float*)d_in[22];
    const float* ln2_a     = (const float*)d_in[23];
    const float* ln2_b     = (const float*)d_in[24];
    const float* ffn_w1    = (const float*)d_in[25];
    const float* ffn_b1    = (const float*)d_in[26];
    const float* ffn_w2    = (const float*)d_in[27];
    const float* ffn_b2    = (const float*)d_in[28];
    const float* out_w     = (const float*)d_in[29];
    const float* out_b     = (const float*)d_in[30];
    float* out = (float*)d_out;

    float *ph,*pq;
    __half *pk1,*pk2,*pv,*phn,*ptemb,*pctx,*pffn,*phh;
    __half *wq,*wk,*wt,*wv_,*wo,*w1,*w2,*wout;
    cudaGetSymbolAddress((void**)&ph,    g_h);
    cudaGetSymbolAddress((void**)&pq,    g_q);
    cudaGetSymbolAddress((void**)&pk1,   g_k1h);
    cudaGetSymbolAddress((void**)&pk2,   g_k2h);
    cudaGetSymbolAddress((void**)&pv,    g_vh);
    cudaGetSymbolAddress((void**)&phn,   g_hn_h);
    cudaGetSymbolAddress((void**)&ptemb, g_temb_h);
    cudaGetSymbolAddress((void**)&pctx,  g_ctx_h);
    cudaGetSymbolAddress((void**)&pffn,  g_ffn_h);
    cudaGetSymbolAddress((void**)&phh,   g_hh);
    cudaGetSymbolAddress((void**)&wq,    g_Wqh);
    cudaGetSymbolAddress((void**)&wk,    g_Wkh);
    cudaGetSymbolAddress((void**)&wt,    g_Wth);
    cudaGetSymbolAddress((void**)&wv_,   g_Wvh);
    cudaGetSymbolAddress((void**)&wo,    g_Woh);
    cudaGetSymbolAddress((void**)&w1,    g_w1h);
    cudaGetSymbolAddress((void**)&w2,    g_w2h);
    cudaGetSymbolAddress((void**)&wout,  g_outwh);

    const int attn_smem = SH*DK_*4 + SS*DK_*2 + DK_*KTP*2 + (SH*SS + SS)*4;  // ~59.3 KB
    cudaFuncSetAttribute(attn_kernel, cudaFuncAttributeMaxDynamicSharedMemorySize, attn_smem);

    // weight conversion: 2 launches (7 small tensors batched + the big out_w)
    const int n7 = 5*(LL*DD*DD/4) + 2*(LL*DFF_*DD/4);
    const int nOut = NOUT*DD/4;
    f2h7_kernel<<<(n7+255)/256, 256>>>(Wq, Wk, Wt, Wv, Wo, ffn_w1, ffn_w2,
                                       wq, wk, wt, wv_, wo, w1, w2);
    f2h_kernel<<<(nOut+255)/256, 256>>>(out_w, wout, nOut);

    embed_kernel<<<MM, 256>>>(x, times, token_emb, pos_emb, sel_w, sel_b,
                              time_w, time_b, per_w, per_b);

    dim3 gF(8, 25);            // 128x128 tiles, N=1024
    dim3 gS(4, 50);            // 64x64 tiles, N=256
    dim3 gQKTV(2, 25, 4);
    for (int l = 0; l < LL; l++) {
        ln_kernel<<<MM, 256>>>(ph, ln1_a + l*DD, ln1_b + l*DD, phn);
        qktv_gemm<<<gQKTV, 256>>>(phn, ptemb,
                                  wq + (size_t)l*DD*DD, wk + (size_t)l*DD*DD,
                                  wt + (size_t)l*DD*DD, wv_ + (size_t)l*DD*DD,
                                  bq + l*DD, bk + l*DD, bt + l*DD, bv + l*DD,
                                  pq, pk1, pk2, pv);
        attn_kernel<<<dim3(HH, BB, 2), 512, attn_smem>>>(pq, pk1, pk2, pv, x,
                                                         mask_log + l*SS*SS, pctx);
        gemm_s<<<gS, 128>>>(pctx, wo + (size_t)l*DD*DD, bo + l*DD, ph, ph, nullptr, DD, DD, 2);
        ln_kernel<<<MM, 256>>>(ph, ln2_a + l*DD, ln2_b + l*DD, phn);
        gemm_mma<<<gF, 256>>>(phn, w1 + (size_t)l*DFF_*DD, ffn_b1 + l*DFF_,
                              nullptr, nullptr, pffn, DFF_, DD, 1);
        gemm_s<<<gS, 128>>>(pffn, w2 + (size_t)l*DD*DFF_, ffn_b2 + l*DD, ph, ph, phh, DD, DFF_, 3);
    }
    gemm_mma<<<dim3(391, 25), 256>>>(phh, wout, out_b, nullptr, out, nullptr, NOUT, DD, 0);
}